// round 15
// baseline (speedup 1.0000x reference)
#include <cuda_runtime.h>

// ContMix fused, fp32 + f32x2 FMA everywhere, attn-in-registers,
// channel-contiguous halo (vector LDS mixing), WK-factored logits.
// B=32, C=64, H=W=56, G=4, C2=32, SMK=5, K=7, SCALE=0.25

#define NB 32
#define NC 64
#define NH 56
#define NW 56

__device__ float g_kg[NB * 32 * 49];
__device__ float g_wk[NB * 32 * 80];            // WK[b][g*8+c][m(padded 80)]
__device__ float g_lep[NB * NC * NH * NW];      // lepe+bn output

// Smem layout for k_main (float offsets; float4 regions 16B-aligned)
#define O_WPB   0        // 80 (padded)
#define O_WK    80       // 32*80 = 2560
#define O_DYW   2640     // 4096
#define O_DYS   6736     // 64
#define O_DYB   6800     // 64
#define O_RPB1  6864     // 324
#define O_RPB2  7188     // 676
#define O_M     7864     // 3808 = 56*68 (union: wqT 1024 + qb 32 during P0..P3)
#define O_WQT   O_M
#define O_QB    (O_M + 1024)
#define O_XCH   11672    // halo [rr 0..6][wi 0..61][ch 0..31 pad 36] = 7*62*36 = 15624
#define SMEM_FLOATS 27296
#define SMEM_BYTES (SMEM_FLOATS * 4)   // 109184 B -> 2 CTAs/SM

// clamp helper matching numpy repeat-based bias index construction
__device__ __forceinline__ int bcl(int r, int kh, int k) {
    return r < kh ? r : (r >= 56 - kh ? (k - 1) - (55 - r) : kh);
}

__global__ void k_pool(const float* __restrict__ x,
                       const float* __restrict__ wk_w,
                       const float* __restrict__ wk_s,
                       const float* __restrict__ wk_b,
                       float* __restrict__ kg) {
    const int s = blockIdx.x;      // row-band / l-row 0..6
    const int b = blockIdx.y;
    const int tid = threadIdx.x;
    const int l0 = s * 7;
    __shared__ float s_x[32 * 8 * 56];   // [ic][r][w]
    __shared__ float s_pool[32 * 7];
    __shared__ float s_wk[32 * 32];
    for (int t = tid; t < 1024; t += 256) s_wk[t] = wk_w[t];
    {
        const float4* src = (const float4*)(x + (((size_t)b * NC + 32) * NH + s * 8) * NW);
        float4* dst = (float4*)s_x;
        for (int t = tid; t < 3584; t += 256) {
            int ic = t / 112, rem = t - ic * 112;
            dst[t] = src[(size_t)ic * 784 + rem];
        }
    }
    __syncthreads();
    if (tid < 224) {
        int ic = tid / 7, lj = tid % 7;
        const float4* base = (const float4*)(s_x + ic * 448 + lj * 8);
        float sum = 0.f;
        #pragma unroll
        for (int y = 0; y < 8; y++) {
            float4 a = base[y * 14];
            float4 c = base[y * 14 + 1];
            sum += a.x + a.y + a.z + a.w + c.x + c.y + c.z + c.w;
        }
        s_pool[ic * 7 + lj] = sum * (1.0f / 64.0f);
    }
    __syncthreads();
    if (tid < 224) {
        int oc = tid / 7, lj = tid % 7;
        float acc = 0.f;
        #pragma unroll
        for (int ic = 0; ic < 32; ic++)
            acc += s_wk[oc * 32 + ic] * s_pool[ic * 7 + lj];
        kg[(size_t)b * 1568 + oc * 49 + l0 + lj] = acc * wk_s[oc] + wk_b[oc];
    }
}

// WK[b][chan][m] = sum_l wp_w[m*49+l] * kg[b][chan*49+l]   (m padded to 80)
__global__ void k_wk(const float* __restrict__ wp_w,
                     const float* __restrict__ kg,
                     float* __restrict__ wk) {
    const int b = blockIdx.x;
    const int tid = threadIdx.x;
    __shared__ float s_kg[1568];
    __shared__ float s_wp[3626];
    for (int t = tid; t < 1568; t += 256) s_kg[t] = kg[(size_t)b * 1568 + t];
    for (int t = tid; t < 3626; t += 256) s_wp[t] = wp_w[t];
    __syncthreads();
    for (int t = tid; t < 2560; t += 256) {
        int chan = t / 80, m = t % 80;
        float acc = 0.f;
        if (m < 74) {
            const float* wr = s_wp + m * 49;
            const float* kr = s_kg + chan * 49;
            #pragma unroll
            for (int l = 0; l < 49; l++) acc += wr[l] * kr[l];
        }
        wk[(size_t)b * 2560 + t] = acc;
    }
}

// Depthwise 7x7 lepe conv + bn -> g_lep.
__global__ __launch_bounds__(256, 3)
void k_lepe(const float* __restrict__ x,
            const float* __restrict__ lepe_w, const float* __restrict__ lepe_b,
            const float* __restrict__ lepe_s, const float* __restrict__ lepe_bb,
            float* __restrict__ lep) {
    const int c = blockIdx.x;
    const int b = blockIdx.y;
    const int tid = threadIdx.x;
    __shared__ float tile[62 * 64];
    __shared__ float s_lw[49];
    const float* src = x + ((size_t)b * NC + c) * (NH * NW);
    for (int t = tid; t < 62 * 64; t += 256) {
        int r = t >> 6, w = t & 63;
        int gy = r - 3, gx = w - 3;
        float v = 0.f;
        if ((unsigned)gy < 56u && (unsigned)gx < 56u) v = src[gy * 56 + gx];
        tile[t] = v;
    }
    if (tid < 49) s_lw[tid] = lepe_w[c * 49 + tid];
    __syncthreads();
    if (tid < 224) {
        const float scl = lepe_s[c];
        const float off = lepe_b[c] * scl + lepe_bb[c];
        const int r = tid >> 2;
        const int w0 = (tid & 3) * 14;
        float acc[14];
        #pragma unroll
        for (int k = 0; k < 14; k++) acc[k] = 0.f;
        #pragma unroll
        for (int dh = 0; dh < 7; dh++) {
            const float* trow = tile + (r + dh) * 64 + w0;
            float win[20];
            #pragma unroll
            for (int j = 0; j < 20; j++) win[j] = trow[j];
            float lw[7];
            #pragma unroll
            for (int j = 0; j < 7; j++) lw[j] = s_lw[dh * 7 + j];
            #pragma unroll
            for (int k = 0; k < 14; k++) {
                #pragma unroll
                for (int dw = 0; dw < 7; dw++) acc[k] += lw[dw] * win[k + dw];
            }
        }
        float* dst = lep + ((size_t)b * NC + c) * (NH * NW) + r * 56 + w0;
        #pragma unroll
        for (int k = 0; k < 14; k++) dst[k] = acc[k] * scl + off;
    }
}

__global__ __launch_bounds__(256, 2)
void k_main(const float* __restrict__ x,
            const float* __restrict__ wq_w, const float* __restrict__ wq_s,
            const float* __restrict__ wq_b,
            const float* __restrict__ wp_b,
            const float* __restrict__ rpb1, const float* __restrict__ rpb2,
            const float* __restrict__ dy_w, const float* __restrict__ dy_s,
            const float* __restrict__ dy_b,
            const float* __restrict__ wkmat,
            const float* __restrict__ lep,
            float* __restrict__ out) {
    extern __shared__ float sm[];
    const int h = blockIdx.x;
    const int b = blockIdx.y;
    const int tid = threadIdx.x;

    float* s_wpb  = sm + O_WPB;
    float* s_wk   = sm + O_WK;
    float* s_dyw  = sm + O_DYW;
    float* s_dys  = sm + O_DYS;
    float* s_dyb  = sm + O_DYB;
    float* s_rpb1 = sm + O_RPB1;
    float* s_rpb2 = sm + O_RPB2;
    float* s_m    = sm + O_M;
    float* s_wqT  = sm + O_WQT;   // union with s_m (valid until post-qproj barrier)
    float* s_qb   = sm + O_QB;
    float* s_xch  = sm + O_XCH;

    const int warp = tid >> 5;
    const int lane = tid & 31;

    // ---- P0: stage weights + half0 halo (channels 0..31, rows 1..5) ----
    for (int t = tid; t < 1024; t += 256) {
        int i = t >> 5, o = t & 31;
        s_wqT[t] = wq_w[o * 32 + i] * 0.25f * wq_s[o];
    }
    if (tid < 32) s_qb[tid] = 0.25f * wq_b[tid];
    if (tid < 80) s_wpb[tid] = (tid < 74) ? wp_b[tid] : 0.f;
    for (int t = tid; t < 2560; t += 256) s_wk[t] = wkmat[(size_t)b * 2560 + t];
    for (int t = tid; t < 4096; t += 256) s_dyw[t] = dy_w[t];
    if (tid < 64) { s_dys[tid] = dy_s[tid]; s_dyb[tid] = dy_b[tid]; }
    for (int t = tid; t < 324; t += 256) s_rpb1[t] = rpb1[t];
    for (int t = tid; t < 676; t += 256) s_rpb2[t] = rpb2[t];

    // halo layout: s_xch[(rr*62 + wi)*36 + ch]
    #pragma unroll
    for (int c4 = 0; c4 < 4; c4++) {
        int ch = warp * 4 + c4;
        const float* src = x + ((size_t)b * NC + ch) * (NH * NW);
        #pragma unroll
        for (int rr = 1; rr <= 5; rr++) {
            int gy = h - 3 + rr;
            bool vy = (unsigned)gy < 56u;
            #pragma unroll
            for (int k = 0; k < 2; k++) {
                int wi = lane + k * 32;
                if (wi < 62) {
                    int gx = wi - 3;
                    float v = (vy && (unsigned)gx < 56u) ? src[gy * NW + gx] : 0.f;
                    s_xch[(rr * 62 + wi) * 36 + ch] = v;
                }
            }
        }
    }
    __syncthreads();

    const int p = tid % 56;
    const int g = tid / 56;   // valid when tid < 224

    // ---- P3a: q projection (reads wqT union + halo center row) ----
    float qr[8];
    if (tid < 224) {
        #pragma unroll
        for (int c = 0; c < 8; c++) qr[c] = s_qb[g * 8 + c];
        #pragma unroll
        for (int i = 0; i < 32; i++) {
            float xv = s_xch[(3 * 62 + p + 3) * 36 + i];
            const float4* w = (const float4*)(s_wqT + i * 32 + g * 8);
            float4 w0 = w[0], w1 = w[1];
            qr[0] += w0.x * xv; qr[1] += w0.y * xv; qr[2] += w0.z * xv; qr[3] += w0.w * xv;
            qr[4] += w1.x * xv; qr[5] += w1.y * xv; qr[6] += w1.z * xv; qr[7] += w1.w * xv;
        }
    }
    __syncthreads();   // wqT/qb dead; s_m region now writable

    // ---- P3b: WK-GEMM (K=8, f32x2) + rpb + dual softmax + P5a (5x5 mixing) ----
    float attn[74];
    if (tid < 224) {
        #pragma unroll
        for (int half = 0; half < 2; half++) {
            const int M0 = half * 40;
            unsigned long long acc2[20];
            #pragma unroll
            for (int mm = 0; mm < 20; mm++) {
                float b0 = s_wpb[M0 + 2 * mm], b1 = s_wpb[M0 + 2 * mm + 1];
                asm("mov.b64 %0, {%1, %2};" : "=l"(acc2[mm]) : "f"(b0), "f"(b1));
            }
            #pragma unroll
            for (int c = 0; c < 8; c++) {
                unsigned long long vv;
                asm("mov.b64 %0, {%1, %1};" : "=l"(vv) : "f"(qr[c]));
                const ulonglong2* w2 = (const ulonglong2*)(s_wk + (g * 8 + c) * 80 + M0);
                #pragma unroll
                for (int mm = 0; mm < 10; mm++) {
                    ulonglong2 w = w2[mm];
                    asm("fma.rn.f32x2 %0, %1, %2, %0;" : "+l"(acc2[2 * mm])     : "l"(w.x), "l"(vv));
                    asm("fma.rn.f32x2 %0, %1, %2, %0;" : "+l"(acc2[2 * mm + 1]) : "l"(w.y), "l"(vv));
                }
            }
            #pragma unroll
            for (int mm = 0; mm < 20; mm++) {
                float f0, f1;
                asm("mov.b64 {%0, %1}, %2;" : "=f"(f0), "=f"(f1) : "l"(acc2[mm]));
                int idx = M0 + 2 * mm;
                if (idx < 74)     attn[idx] = f0;
                if (idx + 1 < 74) attn[idx + 1] = f1;
            }
        }

        // relative position bias (derived from numpy _bias_idx incl. [::-1])
        int bh5 = bcl(55 - h, 2, 5), bw5 = bcl(55 - p, 2, 5);
        int bh7 = bcl(55 - h, 3, 7), bw7 = bcl(55 - p, 3, 7);
        const float* r1 = s_rpb1 + g * 81;
        const float* r2 = s_rpb2 + g * 169;
        #pragma unroll
        for (int m = 0; m < 25; m++) {
            int dh = m / 5, dw = m % 5;
            attn[m] += r1[(bh5 + dh) * 9 + bw5 + dw];
        }
        #pragma unroll
        for (int j = 0; j < 49; j++) {
            int dh = j / 7, dw = j % 7;
            attn[25 + j] += r2[(bh7 + dh) * 13 + bw7 + dw];
        }
        // softmax over taps [0,25)
        {
            float mx = -1e30f;
            #pragma unroll
            for (int m = 0; m < 25; m++) mx = fmaxf(mx, attn[m]);
            float s = 0.f;
            #pragma unroll
            for (int m = 0; m < 25; m++) { attn[m] = __expf(attn[m] - mx); s += attn[m]; }
            float inv = 1.0f / s;
            #pragma unroll
            for (int m = 0; m < 25; m++) attn[m] *= inv;
        }
        // softmax over taps [25,74)
        {
            float mx = -1e30f;
            #pragma unroll
            for (int m = 25; m < 74; m++) mx = fmaxf(mx, attn[m]);
            float s = 0.f;
            #pragma unroll
            for (int m = 25; m < 74; m++) { attn[m] = __expf(attn[m] - mx); s += attn[m]; }
            float inv = 1.0f / s;
            #pragma unroll
            for (int m = 25; m < 74; m++) attn[m] *= inv;
        }

        // ---- P5a: 5x5 mixing, all 8 group channels via 2x LDS.128 per tap ----
        {
            unsigned long long ae0 = 0, ae1 = 0, ae2 = 0, ae3 = 0;   // even taps
            unsigned long long ao0 = 0, ao1 = 0, ao2 = 0, ao3 = 0;   // odd taps
            #pragma unroll
            for (int dh = 1; dh <= 5; dh++) {
                const char* rowb = (const char*)(s_xch + (dh * 62 + p) * 36 + g * 8);
                #pragma unroll
                for (int dw = 1; dw <= 5; dw++) {
                    ulonglong2 wlo = *(const ulonglong2*)(rowb + dw * 144);
                    ulonglong2 whi = *(const ulonglong2*)(rowb + dw * 144 + 16);
                    unsigned long long vv;
                    asm("mov.b64 %0, {%1, %1};" : "=l"(vv) : "f"(attn[(dh - 1) * 5 + (dw - 1)]));
                    if (dw & 1) {
                        asm("fma.rn.f32x2 %0, %1, %2, %0;" : "+l"(ao0) : "l"(wlo.x), "l"(vv));
                        asm("fma.rn.f32x2 %0, %1, %2, %0;" : "+l"(ao1) : "l"(wlo.y), "l"(vv));
                        asm("fma.rn.f32x2 %0, %1, %2, %0;" : "+l"(ao2) : "l"(whi.x), "l"(vv));
                        asm("fma.rn.f32x2 %0, %1, %2, %0;" : "+l"(ao3) : "l"(whi.y), "l"(vv));
                    } else {
                        asm("fma.rn.f32x2 %0, %1, %2, %0;" : "+l"(ae0) : "l"(wlo.x), "l"(vv));
                        asm("fma.rn.f32x2 %0, %1, %2, %0;" : "+l"(ae1) : "l"(wlo.y), "l"(vv));
                        asm("fma.rn.f32x2 %0, %1, %2, %0;" : "+l"(ae2) : "l"(whi.x), "l"(vv));
                        asm("fma.rn.f32x2 %0, %1, %2, %0;" : "+l"(ae3) : "l"(whi.y), "l"(vv));
                    }
                }
            }
            asm("add.rn.f32x2 %0, %0, %1;" : "+l"(ae0) : "l"(ao0));
            asm("add.rn.f32x2 %0, %0, %1;" : "+l"(ae1) : "l"(ao1));
            asm("add.rn.f32x2 %0, %0, %1;" : "+l"(ae2) : "l"(ao2));
            asm("add.rn.f32x2 %0, %0, %1;" : "+l"(ae3) : "l"(ao3));
            float f0, f1, f2, f3, f4, f5, f6, f7;
            asm("mov.b64 {%0, %1}, %2;" : "=f"(f0), "=f"(f1) : "l"(ae0));
            asm("mov.b64 {%0, %1}, %2;" : "=f"(f2), "=f"(f3) : "l"(ae1));
            asm("mov.b64 {%0, %1}, %2;" : "=f"(f4), "=f"(f5) : "l"(ae2));
            asm("mov.b64 {%0, %1}, %2;" : "=f"(f6), "=f"(f7) : "l"(ae3));
            float4* dst = (float4*)(s_m + p * 68 + g * 8);
            dst[0] = make_float4(f0, f1, f2, f3);
            dst[1] = make_float4(f4, f5, f6, f7);
        }
    }
    __syncthreads();   // all half-0 halo reads done

    // ---- stage half1 halo (channels 32..63, rows 0..6) ----
    #pragma unroll
    for (int c4 = 0; c4 < 4; c4++) {
        int ch = warp * 4 + c4;
        const float* src = x + ((size_t)b * NC + 32 + ch) * (NH * NW);
        #pragma unroll
        for (int rr = 0; rr < 7; rr++) {
            int gy = h - 3 + rr;
            bool vy = (unsigned)gy < 56u;
            #pragma unroll
            for (int k = 0; k < 2; k++) {
                int wi = lane + k * 32;
                if (wi < 62) {
                    int gx = wi - 3;
                    float v = (vy && (unsigned)gx < 56u) ? src[gy * NW + gx] : 0.f;
                    s_xch[(rr * 62 + wi) * 36 + ch] = v;
                }
            }
        }
    }
    __syncthreads();

    // ---- P5b: 7x7 mixing for the 8 half-1 channels of group g ----
    if (tid < 224) {
        unsigned long long ae0 = 0, ae1 = 0, ae2 = 0, ae3 = 0;
        unsigned long long ao0 = 0, ao1 = 0, ao2 = 0, ao3 = 0;
        #pragma unroll
        for (int dh = 0; dh < 7; dh++) {
            const char* rowb = (const char*)(s_xch + (dh * 62 + p) * 36 + g * 8);
            #pragma unroll
            for (int dw = 0; dw < 7; dw++) {
                ulonglong2 wlo = *(const ulonglong2*)(rowb + dw * 144);
                ulonglong2 whi = *(const ulonglong2*)(rowb + dw * 144 + 16);
                unsigned long long vv;
                asm("mov.b64 %0, {%1, %1};" : "=l"(vv) : "f"(attn[25 + dh * 7 + dw]));
                if (dw & 1) {
                    asm("fma.rn.f32x2 %0, %1, %2, %0;" : "+l"(ao0) : "l"(wlo.x), "l"(vv));
                    asm("fma.rn.f32x2 %0, %1, %2, %0;" : "+l"(ao1) : "l"(wlo.y), "l"(vv));
                    asm("fma.rn.f32x2 %0, %1, %2, %0;" : "+l"(ao2) : "l"(whi.x), "l"(vv));
                    asm("fma.rn.f32x2 %0, %1, %2, %0;" : "+l"(ao3) : "l"(whi.y), "l"(vv));
                } else {
                    asm("fma.rn.f32x2 %0, %1, %2, %0;" : "+l"(ae0) : "l"(wlo.x), "l"(vv));
                    asm("fma.rn.f32x2 %0, %1, %2, %0;" : "+l"(ae1) : "l"(wlo.y), "l"(vv));
                    asm("fma.rn.f32x2 %0, %1, %2, %0;" : "+l"(ae2) : "l"(whi.x), "l"(vv));
                    asm("fma.rn.f32x2 %0, %1, %2, %0;" : "+l"(ae3) : "l"(whi.y), "l"(vv));
                }
            }
        }
        asm("add.rn.f32x2 %0, %0, %1;" : "+l"(ae0) : "l"(ao0));
        asm("add.rn.f32x2 %0, %0, %1;" : "+l"(ae1) : "l"(ao1));
        asm("add.rn.f32x2 %0, %0, %1;" : "+l"(ae2) : "l"(ao2));
        asm("add.rn.f32x2 %0, %0, %1;" : "+l"(ae3) : "l"(ao3));
        float f0, f1, f2, f3, f4, f5, f6, f7;
        asm("mov.b64 {%0, %1}, %2;" : "=f"(f0), "=f"(f1) : "l"(ae0));
        asm("mov.b64 {%0, %1}, %2;" : "=f"(f2), "=f"(f3) : "l"(ae1));
        asm("mov.b64 {%0, %1}, %2;" : "=f"(f4), "=f"(f5) : "l"(ae2));
        asm("mov.b64 {%0, %1}, %2;" : "=f"(f6), "=f"(f7) : "l"(ae3));
        float4* dst = (float4*)(s_m + p * 68 + 32 + g * 8);
        dst[0] = make_float4(f0, f1, f2, f3);
        dst[1] = make_float4(f4, f5, f6, f7);
    }
    __syncthreads();

    // ---- P6: dy 64x64 GEMM (float4) + bn + lepe(global) ----
    if (tid < 224) {
        const float* lepb = lep + ((size_t)b * NC) * (NH * NW) + h * NW + p;
        const float4* m4 = (const float4*)(s_m + p * 68);
        #pragma unroll
        for (int k = 0; k < 4; k++) {
            int o0 = (k * 4 + g) * 4;
            float l0 = lepb[(o0 + 0) * 3136];
            float l1 = lepb[(o0 + 1) * 3136];
            float l2 = lepb[(o0 + 2) * 3136];
            float l3 = lepb[(o0 + 3) * 3136];
            const float4* w0 = (const float4*)(s_dyw + (o0 + 0) * 64);
            const float4* w1 = (const float4*)(s_dyw + (o0 + 1) * 64);
            const float4* w2 = (const float4*)(s_dyw + (o0 + 2) * 64);
            const float4* w3 = (const float4*)(s_dyw + (o0 + 3) * 64);
            float a0 = 0.f, a1 = 0.f, a2 = 0.f, a3 = 0.f;
            #pragma unroll
            for (int i = 0; i < 16; i++) {
                float4 mv = m4[i];
                float4 v0 = w0[i], v1 = w1[i], v2 = w2[i], v3 = w3[i];
                a0 += v0.x * mv.x + v0.y * mv.y + v0.z * mv.z + v0.w * mv.w;
                a1 += v1.x * mv.x + v1.y * mv.y + v1.z * mv.z + v1.w * mv.w;
                a2 += v2.x * mv.x + v2.y * mv.y + v2.z * mv.z + v2.w * mv.w;
                a3 += v3.x * mv.x + v3.y * mv.y + v3.z * mv.z + v3.w * mv.w;
            }
            size_t base = (((size_t)b * NC + o0) * NH + h) * NW + p;
            out[base + 0 * 3136] = a0 * s_dys[o0 + 0] + s_dyb[o0 + 0] + l0;
            out[base + 1 * 3136] = a1 * s_dys[o0 + 1] + s_dyb[o0 + 1] + l1;
            out[base + 2 * 3136] = a2 * s_dys[o0 + 2] + s_dyb[o0 + 2] + l2;
            out[base + 3 * 3136] = a3 * s_dys[o0 + 3] + s_dyb[o0 + 3] + l3;
        }
    }
}

extern "C" void kernel_launch(void* const* d_in, const int* in_sizes, int n_in,
                              void* d_out, int out_size) {
    const float* x       = (const float*)d_in[0];
    const float* lepe_w  = (const float*)d_in[1];
    const float* lepe_b  = (const float*)d_in[2];
    const float* lepe_s  = (const float*)d_in[3];
    const float* lepe_bb = (const float*)d_in[4];
    const float* wq_w    = (const float*)d_in[5];
    const float* wq_s    = (const float*)d_in[6];
    const float* wq_b    = (const float*)d_in[7];
    const float* wk_w    = (const float*)d_in[8];
    const float* wk_s    = (const float*)d_in[9];
    const float* wk_b    = (const float*)d_in[10];
    const float* wp_w    = (const float*)d_in[11];
    const float* wp_b    = (const float*)d_in[12];
    const float* rpb1    = (const float*)d_in[13];
    const float* rpb2    = (const float*)d_in[14];
    const float* dy_w    = (const float*)d_in[15];
    const float* dy_s    = (const float*)d_in[16];
    const float* dy_b    = (const float*)d_in[17];
    float* out = (float*)d_out;

    float* kgp = nullptr;
    cudaGetSymbolAddress((void**)&kgp, g_kg);
    float* wkp = nullptr;
    cudaGetSymbolAddress((void**)&wkp, g_wk);
    float* lepp = nullptr;
    cudaGetSymbolAddress((void**)&lepp, g_lep);

    cudaFuncSetAttribute(k_main, cudaFuncAttributeMaxDynamicSharedMemorySize, SMEM_BYTES);

    k_pool<<<dim3(7, NB), 256>>>(x, wk_w, wk_s, wk_b, kgp);
    k_wk<<<NB, 256>>>(wp_w, kgp, wkp);
    k_lepe<<<dim3(NC, NB), 256>>>(x, lepe_w, lepe_b, lepe_s, lepe_bb, lepp);
    k_main<<<dim3(NH, NB), 256, SMEM_BYTES>>>(
        x, wq_w, wq_s, wq_b, wp_b,
        rpb1, rpb2, dy_w, dy_s, dy_b, wkp, lepp, out);
}

// round 16
// speedup vs baseline: 1.5072x; 1.5072x over previous
#include <cuda_runtime.h>

// ContMix fused, fp32 + f32x2 FMA, attn-in-registers, bulk-staged P5 (2 halves),
// WK-factored logits, co-scheduled lepe+pool prep kernel.
// B=32, C=64, H=W=56, G=4, C2=32, SMK=5, K=7, SCALE=0.25

#define NB 32
#define NC 64
#define NH 56
#define NW 56

__device__ float g_kg[NB * 32 * 49];
__device__ float g_wk[NB * 32 * 80];            // WK[b][g*8+c][m(padded 80)]
__device__ float g_lep[NB * NC * NH * NW];      // lepe+bn output

// Smem layout for k_main (float offsets; float4 regions 16B-aligned)
#define O_WQT   0        // 1024  wqT[i*32+o] (scale-folded)
#define O_QB    1024     // 32    0.25*wq_b
#define O_WPB   1056     // 80 (padded)
#define O_WK    1136     // 32*80 = 2560
#define O_DYW   3696     // 4096
#define O_DYS   7792     // 64
#define O_DYB   7856     // 64
#define O_RPB1  7920     // 324
#define O_RPB2  8244     // 676
#define O_M     8920     // 56*68 = 3808
#define O_XCH   12728    // 32ch x 7rows x 64 = 14336 halo buffer (one half)
#define SMEM_FLOATS 27064
#define SMEM_BYTES (SMEM_FLOATS * 4)

// clamp helper matching numpy repeat-based bias index construction
__device__ __forceinline__ int bcl(int r, int kh, int k) {
    return r < kh ? r : (r >= 56 - kh ? (k - 1) - (55 - r) : kh);
}

// Co-scheduled prep: blocks [0, 2048) do depthwise-7x7 lepe+bn -> g_lep,
// blocks [2048, 2272) do 8x8 avgpool + wk proj -> g_kg. One launch, so the
// tiny pool workload hides under the lepe workload instead of serializing.
__global__ __launch_bounds__(256)
void k_prep(const float* __restrict__ x,
            const float* __restrict__ lepe_w, const float* __restrict__ lepe_b,
            const float* __restrict__ lepe_s, const float* __restrict__ lepe_bb,
            const float* __restrict__ wk_w, const float* __restrict__ wk_s,
            const float* __restrict__ wk_b,
            float* __restrict__ lep, float* __restrict__ kg) {
    __shared__ float u_buf[62 * 64];     // lepe tile  (pool uses first 1248)
    __shared__ float u_aux[1024 + 49];   // pool: s_wk | lepe: s_lw (first 49)
    const int tid = threadIdx.x;
    const int bid = blockIdx.x;

    if (bid < 2048) {
        // ---------------- lepe block: c = bid>>5, b = bid&31 ----------------
        const int c = bid >> 5;
        const int b = bid & 31;
        float* tile = u_buf;
        float* s_lw = u_aux;
        const float* src = x + ((size_t)b * NC + c) * (NH * NW);
        for (int t = tid; t < 62 * 64; t += 256) {
            int r = t >> 6, w = t & 63;
            int gy = r - 3, gx = w - 3;
            float v = 0.f;
            if ((unsigned)gy < 56u && (unsigned)gx < 56u) v = src[gy * 56 + gx];
            tile[t] = v;
        }
        if (tid < 49) s_lw[tid] = lepe_w[c * 49 + tid];
        __syncthreads();
        if (tid < 224) {
            const float scl = lepe_s[c];
            const float off = lepe_b[c] * scl + lepe_bb[c];
            const int r = tid >> 2;
            const int w0 = (tid & 3) * 14;
            float acc[14];
            #pragma unroll
            for (int k = 0; k < 14; k++) acc[k] = 0.f;
            #pragma unroll
            for (int dh = 0; dh < 7; dh++) {
                const float* trow = tile + (r + dh) * 64 + w0;
                float win[20];
                #pragma unroll
                for (int j = 0; j < 20; j++) win[j] = trow[j];
                float lw[7];
                #pragma unroll
                for (int j = 0; j < 7; j++) lw[j] = s_lw[dh * 7 + j];
                #pragma unroll
                for (int k = 0; k < 14; k++) {
                    #pragma unroll
                    for (int dw = 0; dw < 7; dw++) acc[k] += lw[dw] * win[k + dw];
                }
            }
            float* dst = lep + ((size_t)b * NC + c) * (NH * NW) + r * 56 + w0;
            #pragma unroll
            for (int k = 0; k < 14; k++) dst[k] = acc[k] * scl + off;
        }
    } else {
        // ---------------- pool block: t = bid-2048; s = t%7, b = t/7 --------
        const int t0 = bid - 2048;
        const int s = t0 % 7;
        const int b = t0 / 7;
        const int l0 = s * 7;
        float* s_pool = u_buf;           // 224 floats
        float* s_wk   = u_aux;           // 1024 floats
        for (int t = tid; t < 1024; t += 256) s_wk[t] = wk_w[t];
        if (tid < 224) {
            int ic = tid / 7, lj = tid % 7;
            int l = l0 + lj;
            int i = l / 7, j = l % 7;
            const float4* base = (const float4*)(x + (((size_t)b * NC + 32 + ic) * NH + i * 8) * NW + j * 8);
            float sum = 0.f;
            #pragma unroll
            for (int y = 0; y < 8; y++) {
                float4 a = base[y * 14];
                float4 c = base[y * 14 + 1];
                sum += a.x + a.y + a.z + a.w + c.x + c.y + c.z + c.w;
            }
            s_pool[ic * 7 + lj] = sum * (1.0f / 64.0f);
        }
        __syncthreads();
        if (tid < 224) {
            int oc = tid / 7, lj = tid % 7;
            float acc = 0.f;
            #pragma unroll
            for (int ic = 0; ic < 32; ic++)
                acc += s_wk[oc * 32 + ic] * s_pool[ic * 7 + lj];
            kg[(size_t)b * 1568 + oc * 49 + l0 + lj] = acc * wk_s[oc] + wk_b[oc];
        }
    }
}

// WK[b][chan][m] = sum_l wp_w[m*49+l] * kg[b][chan*49+l]   (m padded to 80)
__global__ void k_wk(const float* __restrict__ wp_w,
                     const float* __restrict__ kg,
                     float* __restrict__ wk) {
    const int b = blockIdx.x;
    const int tid = threadIdx.x;
    __shared__ float s_kg[1568];
    __shared__ float s_wp[3626];
    for (int t = tid; t < 1568; t += 256) s_kg[t] = kg[(size_t)b * 1568 + t];
    for (int t = tid; t < 3626; t += 256) s_wp[t] = wp_w[t];
    __syncthreads();
    for (int t = tid; t < 2560; t += 256) {
        int chan = t / 80, m = t % 80;
        float acc = 0.f;
        if (m < 74) {
            const float* wr = s_wp + m * 49;
            const float* kr = s_kg + chan * 49;
            #pragma unroll
            for (int l = 0; l < 49; l++) acc += wr[l] * kr[l];
        }
        wk[(size_t)b * 2560 + t] = acc;
    }
}

__global__ __launch_bounds__(256, 2)
void k_main(const float* __restrict__ x,
            const float* __restrict__ wq_w, const float* __restrict__ wq_s,
            const float* __restrict__ wq_b,
            const float* __restrict__ wp_b,
            const float* __restrict__ rpb1, const float* __restrict__ rpb2,
            const float* __restrict__ dy_w, const float* __restrict__ dy_s,
            const float* __restrict__ dy_b,
            const float* __restrict__ wkmat,
            const float* __restrict__ lep,
            float* __restrict__ out) {
    extern __shared__ float sm[];
    const int h = blockIdx.x;
    const int b = blockIdx.y;
    const int tid = threadIdx.x;

    float* s_wqT  = sm + O_WQT;
    float* s_qb   = sm + O_QB;
    float* s_wpb  = sm + O_WPB;
    float* s_wk   = sm + O_WK;
    float* s_dyw  = sm + O_DYW;
    float* s_dys  = sm + O_DYS;
    float* s_dyb  = sm + O_DYB;
    float* s_rpb1 = sm + O_RPB1;
    float* s_rpb2 = sm + O_RPB2;
    float* s_m    = sm + O_M;
    float* s_xch  = sm + O_XCH;

    const int warp = tid >> 5;
    const int lane = tid & 31;

    // ---- P0: stage weights + half0 halo (channels 0..31, rows 1..5) ----
    for (int t = tid; t < 1024; t += 256) {
        int i = t >> 5, o = t & 31;
        s_wqT[t] = wq_w[o * 32 + i] * 0.25f * wq_s[o];
    }
    if (tid < 32) s_qb[tid] = 0.25f * wq_b[tid];
    if (tid < 80) s_wpb[tid] = (tid < 74) ? wp_b[tid] : 0.f;
    for (int t = tid; t < 2560; t += 256) s_wk[t] = wkmat[(size_t)b * 2560 + t];
    for (int t = tid; t < 4096; t += 256) s_dyw[t] = dy_w[t];
    if (tid < 64) { s_dys[tid] = dy_s[tid]; s_dyb[tid] = dy_b[tid]; }
    for (int t = tid; t < 324; t += 256) s_rpb1[t] = rpb1[t];
    for (int t = tid; t < 676; t += 256) s_rpb2[t] = rpb2[t];

    // halo staging: warp handles 4 channels, lane covers wi and wi+32
    #pragma unroll
    for (int c4 = 0; c4 < 4; c4++) {
        int ch = warp * 4 + c4;
        const float* src = x + ((size_t)b * NC + ch) * (NH * NW);
        #pragma unroll
        for (int rr = 1; rr <= 5; rr++) {
            int gy = h - 3 + rr;
            bool vy = (unsigned)gy < 56u;
            #pragma unroll
            for (int k = 0; k < 2; k++) {
                int wi = lane + k * 32;
                int gx = wi - 3;
                float v = (vy && (unsigned)gx < 56u) ? src[gy * NW + gx] : 0.f;
                s_xch[ch * 448 + rr * 64 + wi] = v;
            }
        }
    }
    __syncthreads();

    const int p = tid % 56;
    const int g = tid / 56;   // valid when tid < 224

    // ---- P3: q-proj (from halo center row) + WK-GEMM (K=8, f32x2) + rpb + softmax ----
    float attn[74];
    if (tid < 224) {
        float qr[8];
        #pragma unroll
        for (int c = 0; c < 8; c++) qr[c] = s_qb[g * 8 + c];
        #pragma unroll
        for (int i = 0; i < 32; i++) {
            float xv = s_xch[i * 448 + 195 + p];   // row rr=3 (center), wi = p+3
            const float4* w = (const float4*)(s_wqT + i * 32 + g * 8);
            float4 w0 = w[0], w1 = w[1];
            qr[0] += w0.x * xv; qr[1] += w0.y * xv; qr[2] += w0.z * xv; qr[3] += w0.w * xv;
            qr[4] += w1.x * xv; qr[5] += w1.y * xv; qr[6] += w1.z * xv; qr[7] += w1.w * xv;
        }

        #pragma unroll
        for (int half = 0; half < 2; half++) {
            const int M0 = half * 40;
            unsigned long long acc2[20];
            #pragma unroll
            for (int mm = 0; mm < 20; mm++) {
                float b0 = s_wpb[M0 + 2 * mm], b1 = s_wpb[M0 + 2 * mm + 1];
                asm("mov.b64 %0, {%1, %2};" : "=l"(acc2[mm]) : "f"(b0), "f"(b1));
            }
            #pragma unroll
            for (int c = 0; c < 8; c++) {
                unsigned long long vv;
                asm("mov.b64 %0, {%1, %1};" : "=l"(vv) : "f"(qr[c]));
                const ulonglong2* w2 = (const ulonglong2*)(s_wk + (g * 8 + c) * 80 + M0);
                #pragma unroll
                for (int mm = 0; mm < 10; mm++) {
                    ulonglong2 w = w2[mm];
                    asm("fma.rn.f32x2 %0, %1, %2, %0;" : "+l"(acc2[2 * mm])     : "l"(w.x), "l"(vv));
                    asm("fma.rn.f32x2 %0, %1, %2, %0;" : "+l"(acc2[2 * mm + 1]) : "l"(w.y), "l"(vv));
                }
            }
            #pragma unroll
            for (int mm = 0; mm < 20; mm++) {
                float f0, f1;
                asm("mov.b64 {%0, %1}, %2;" : "=f"(f0), "=f"(f1) : "l"(acc2[mm]));
                int idx = M0 + 2 * mm;
                if (idx < 74)     attn[idx] = f0;
                if (idx + 1 < 74) attn[idx + 1] = f1;
            }
        }

        // relative position bias (derived from numpy _bias_idx incl. [::-1])
        int bh5 = bcl(55 - h, 2, 5), bw5 = bcl(55 - p, 2, 5);
        int bh7 = bcl(55 - h, 3, 7), bw7 = bcl(55 - p, 3, 7);
        const float* r1 = s_rpb1 + g * 81;
        const float* r2 = s_rpb2 + g * 169;
        #pragma unroll
        for (int m = 0; m < 25; m++) {
            int dh = m / 5, dw = m % 5;
            attn[m] += r1[(bh5 + dh) * 9 + bw5 + dw];
        }
        #pragma unroll
        for (int j = 0; j < 49; j++) {
            int dh = j / 7, dw = j % 7;
            attn[25 + j] += r2[(bh7 + dh) * 13 + bw7 + dw];
        }
        // softmax over taps [0,25)
        {
            float mx = -1e30f;
            #pragma unroll
            for (int m = 0; m < 25; m++) mx = fmaxf(mx, attn[m]);
            float s = 0.f;
            #pragma unroll
            for (int m = 0; m < 25; m++) { attn[m] = __expf(attn[m] - mx); s += attn[m]; }
            float inv = 1.0f / s;
            #pragma unroll
            for (int m = 0; m < 25; m++) attn[m] *= inv;
        }
        // softmax over taps [25,74)
        {
            float mx = -1e30f;
            #pragma unroll
            for (int m = 25; m < 74; m++) mx = fmaxf(mx, attn[m]);
            float s = 0.f;
            #pragma unroll
            for (int m = 25; m < 74; m++) { attn[m] = __expf(attn[m] - mx); s += attn[m]; }
            float inv = 1.0f / s;
            #pragma unroll
            for (int m = 25; m < 74; m++) attn[m] *= inv;
        }

        // ---- P5a: 5x5 mixing for the 8 half-0 channels of group g ----
        #pragma unroll
        for (int j = 0; j < 8; j++) {
            int ch = g * 8 + j;
            const float* xb = s_xch + ch * 448 + p;
            float mac0 = 0.f, mac1 = 0.f;
            #pragma unroll
            for (int dh = 1; dh <= 5; dh++) {
                #pragma unroll
                for (int dw = 1; dw <= 5; dw++) {
                    float xv = xb[dh * 64 + dw];
                    if (dw & 1) mac0 += attn[(dh - 1) * 5 + (dw - 1)] * xv;
                    else        mac1 += attn[(dh - 1) * 5 + (dw - 1)] * xv;
                }
            }
            s_m[p * 68 + ch] = mac0 + mac1;
        }
    }
    __syncthreads();   // all half-0 halo reads done

    // ---- stage half1 halo (channels 32..63, rows 0..6) ----
    #pragma unroll
    for (int c4 = 0; c4 < 4; c4++) {
        int ch = warp * 4 + c4;
        const float* src = x + ((size_t)b * NC + 32 + ch) * (NH * NW);
        #pragma unroll
        for (int rr = 0; rr < 7; rr++) {
            int gy = h - 3 + rr;
            bool vy = (unsigned)gy < 56u;
            #pragma unroll
            for (int k = 0; k < 2; k++) {
                int wi = lane + k * 32;
                int gx = wi - 3;
                float v = (vy && (unsigned)gx < 56u) ? src[gy * NW + gx] : 0.f;
                s_xch[ch * 448 + rr * 64 + wi] = v;
            }
        }
    }
    __syncthreads();

    // ---- P5b: 7x7 mixing for the 8 half-1 channels of group g ----
    if (tid < 224) {
        #pragma unroll
        for (int j = 0; j < 8; j++) {
            int ch = g * 8 + j;           // buffer slot; output channel = 32 + ch
            const float* xb = s_xch + ch * 448 + p;
            float mac0 = 0.f, mac1 = 0.f;
            #pragma unroll
            for (int dh = 0; dh < 7; dh++) {
                #pragma unroll
                for (int dw = 0; dw < 7; dw++) {
                    float xv = xb[dh * 64 + dw];
                    if (dw & 1) mac0 += attn[25 + dh * 7 + dw] * xv;
                    else        mac1 += attn[25 + dh * 7 + dw] * xv;
                }
            }
            s_m[p * 68 + 32 + ch] = mac0 + mac1;
        }
    }
    __syncthreads();

    // ---- P6: dy 64x64 GEMM (float4) + bn + lepe(global) ----
    if (tid < 224) {
        const float* lepb = lep + ((size_t)b * NC) * (NH * NW) + h * NW + p;
        const float4* m4 = (const float4*)(s_m + p * 68);
        #pragma unroll
        for (int k = 0; k < 4; k++) {
            int o0 = (k * 4 + g) * 4;
            float l0 = lepb[(o0 + 0) * 3136];
            float l1 = lepb[(o0 + 1) * 3136];
            float l2 = lepb[(o0 + 2) * 3136];
            float l3 = lepb[(o0 + 3) * 3136];
            const float4* w0 = (const float4*)(s_dyw + (o0 + 0) * 64);
            const float4* w1 = (const float4*)(s_dyw + (o0 + 1) * 64);
            const float4* w2 = (const float4*)(s_dyw + (o0 + 2) * 64);
            const float4* w3 = (const float4*)(s_dyw + (o0 + 3) * 64);
            float a0 = 0.f, a1 = 0.f, a2 = 0.f, a3 = 0.f;
            #pragma unroll
            for (int i = 0; i < 16; i++) {
                float4 mv = m4[i];
                float4 v0 = w0[i], v1 = w1[i], v2 = w2[i], v3 = w3[i];
                a0 += v0.x * mv.x + v0.y * mv.y + v0.z * mv.z + v0.w * mv.w;
                a1 += v1.x * mv.x + v1.y * mv.y + v1.z * mv.z + v1.w * mv.w;
                a2 += v2.x * mv.x + v2.y * mv.y + v2.z * mv.z + v2.w * mv.w;
                a3 += v3.x * mv.x + v3.y * mv.y + v3.z * mv.z + v3.w * mv.w;
            }
            size_t base = (((size_t)b * NC + o0) * NH + h) * NW + p;
            out[base + 0 * 3136] = a0 * s_dys[o0 + 0] + s_dyb[o0 + 0] + l0;
            out[base + 1 * 3136] = a1 * s_dys[o0 + 1] + s_dyb[o0 + 1] + l1;
            out[base + 2 * 3136] = a2 * s_dys[o0 + 2] + s_dyb[o0 + 2] + l2;
            out[base + 3 * 3136] = a3 * s_dys[o0 + 3] + s_dyb[o0 + 3] + l3;
        }
    }
}

extern "C" void kernel_launch(void* const* d_in, const int* in_sizes, int n_in,
                              void* d_out, int out_size) {
    const float* x       = (const float*)d_in[0];
    const float* lepe_w  = (const float*)d_in[1];
    const float* lepe_b  = (const float*)d_in[2];
    const float* lepe_s  = (const float*)d_in[3];
    const float* lepe_bb = (const float*)d_in[4];
    const float* wq_w    = (const float*)d_in[5];
    const float* wq_s    = (const float*)d_in[6];
    const float* wq_b    = (const float*)d_in[7];
    const float* wk_w    = (const float*)d_in[8];
    const float* wk_s    = (const float*)d_in[9];
    const float* wk_b    = (const float*)d_in[10];
    const float* wp_w    = (const float*)d_in[11];
    const float* wp_b    = (const float*)d_in[12];
    const float* rpb1    = (const float*)d_in[13];
    const float* rpb2    = (const float*)d_in[14];
    const float* dy_w    = (const float*)d_in[15];
    const float* dy_s    = (const float*)d_in[16];
    const float* dy_b    = (const float*)d_in[17];
    float* out = (float*)d_out;

    float* kgp = nullptr;
    cudaGetSymbolAddress((void**)&kgp, g_kg);
    float* wkp = nullptr;
    cudaGetSymbolAddress((void**)&wkp, g_wk);
    float* lepp = nullptr;
    cudaGetSymbolAddress((void**)&lepp, g_lep);

    cudaFuncSetAttribute(k_main, cudaFuncAttributeMaxDynamicSharedMemorySize, SMEM_BYTES);

    k_prep<<<2272, 256>>>(x, lepe_w, lepe_b, lepe_s, lepe_bb,
                          wk_w, wk_s, wk_b, lepp, kgp);
    k_wk<<<NB, 256>>>(wp_w, kgp, wkp);
    k_main<<<dim3(NH, NB), 256, SMEM_BYTES>>>(
        x, wq_w, wq_s, wq_b, wp_b,
        rpb1, rpb2, dy_w, dy_s, dy_b, wkp, lepp, out);
}

// round 17
// speedup vs baseline: 1.5403x; 1.0219x over previous
#include <cuda_runtime.h>

// ContMix fused, fp32 + f32x2 FMA, attn-in-registers, bulk-staged P5 (2 halves,
// channel-paired float2 halo), WK-factored logits, conflict-free paired lepe.
// B=32, C=64, H=W=56, G=4, C2=32, SMK=5, K=7, SCALE=0.25

#define NB 32
#define NC 64
#define NH 56
#define NW 56

__device__ float g_kg[NB * 32 * 49];
__device__ float g_wk[NB * 32 * 80];            // WK[b][g*8+c][m(padded 80)]
__device__ float g_lep[NB * NC * NH * NW];      // lepe+bn output

// Smem layout for k_main (float offsets; float4 regions 16B-aligned)
#define O_WQT   0        // 1024  wqT[i*32+o] (scale-folded)
#define O_QB    1024     // 32    0.25*wq_b
#define O_WPB   1056     // 80 (padded)
#define O_WK    1136     // 32*80 = 2560
#define O_DYW   3696     // 4096
#define O_DYS   7792     // 64
#define O_DYB   7856     // 64
#define O_RPB1  7920     // 324
#define O_RPB2  8244     // 676
#define O_M     8920     // 56*68 = 3808
#define O_XCH   12728    // halo: 16 cq x 449 float2 (pad vs 448 for bank spread)
#define CQS     449
#define SMEM_FLOATS (12728 + 16 * CQS * 2)      // 27096
#define SMEM_BYTES (SMEM_FLOATS * 4)            // 108384 -> 2 CTAs/SM

// clamp helper matching numpy repeat-based bias index construction
__device__ __forceinline__ int bcl(int r, int kh, int k) {
    return r < kh ? r : (r >= 56 - kh ? (k - 1) - (55 - r) : kh);
}

// Co-scheduled prep: blocks [0,1024) = lepe channel-pairs, [1024,1248) = pool.
// Lepe: two smem planes with row stride 65 (conflict-free), f32x2 pair math.
__global__ __launch_bounds__(256, 2)
void k_prep(const float* __restrict__ x,
            const float* __restrict__ lepe_w, const float* __restrict__ lepe_b,
            const float* __restrict__ lepe_s, const float* __restrict__ lepe_bb,
            const float* __restrict__ wk_w, const float* __restrict__ wk_s,
            const float* __restrict__ wk_b,
            float* __restrict__ lep, float* __restrict__ kg) {
    __shared__ __align__(16) float u_smem[2 * 62 * 65 + 112];   // 8172 floats
    const int tid = threadIdx.x;
    const int bid = blockIdx.x;

    if (bid < 1024) {
        // ---- lepe pair block: cp = bid>>5 (channels 2cp, 2cp+1), b = bid&31 ----
        const int cp = bid >> 5;
        const int b = bid & 31;
        const int c0 = cp * 2, c1 = c0 + 1;
        float* tile0 = u_smem;                 // 62*65
        float* tile1 = u_smem + 62 * 65;       // 62*65
        float* s_lw  = u_smem + 2 * 62 * 65;   // 98: [tap*2 + ch]
        const float* s0 = x + ((size_t)b * NC + c0) * (NH * NW);
        const float* s1 = s0 + NH * NW;
        for (int t = tid; t < 3968; t += 256) {
            int r = t >> 6, w = t & 63;
            int gy = r - 3, gx = w - 3;
            float v0 = 0.f, v1 = 0.f;
            if ((unsigned)gy < 56u && (unsigned)gx < 56u) {
                int o = gy * 56 + gx;
                v0 = s0[o]; v1 = s1[o];
            }
            tile0[r * 65 + w] = v0;
            tile1[r * 65 + w] = v1;
        }
        if (tid < 98) {
            int tap = tid >> 1, cc = tid & 1;
            s_lw[tid] = lepe_w[(c0 + cc) * 49 + tap];
        }
        __syncthreads();
        if (tid < 224) {
            const float scl0 = lepe_s[c0];
            const float off0 = lepe_b[c0] * scl0 + lepe_bb[c0];
            const float scl1 = lepe_s[c1];
            const float off1 = lepe_b[c1] * scl1 + lepe_bb[c1];
            const int r = tid >> 2;
            const int w0 = (tid & 3) * 14;
            unsigned long long acc[14];
            #pragma unroll
            for (int k = 0; k < 14; k++) acc[k] = 0ull;
            #pragma unroll
            for (int dh = 0; dh < 7; dh++) {
                const float* t0r = tile0 + (r + dh) * 65 + w0;
                const float* t1r = tile1 + (r + dh) * 65 + w0;
                unsigned long long win[20];
                #pragma unroll
                for (int j = 0; j < 20; j++) {
                    float a = t0r[j], bb = t1r[j];
                    asm("mov.b64 %0, {%1, %2};" : "=l"(win[j]) : "f"(a), "f"(bb));
                }
                unsigned long long lwp[7];
                #pragma unroll
                for (int j = 0; j < 7; j++)
                    lwp[j] = *(const unsigned long long*)(s_lw + (dh * 7 + j) * 2);
                #pragma unroll
                for (int k = 0; k < 14; k++) {
                    #pragma unroll
                    for (int dw = 0; dw < 7; dw++)
                        asm("fma.rn.f32x2 %0, %1, %2, %0;"
                            : "+l"(acc[k]) : "l"(win[k + dw]), "l"(lwp[dw]));
                }
            }
            float* dst0 = lep + ((size_t)b * NC + c0) * (NH * NW) + r * 56 + w0;
            float* dst1 = dst0 + NH * NW;
            #pragma unroll
            for (int k = 0; k < 14; k++) {
                float a, bb;
                asm("mov.b64 {%0, %1}, %2;" : "=f"(a), "=f"(bb) : "l"(acc[k]));
                dst0[k] = a * scl0 + off0;
                dst1[k] = bb * scl1 + off1;
            }
        }
    } else {
        // ---- pool block: t0 = bid-1024; s = t0%7, b = t0/7 ----
        const int t0 = bid - 1024;
        const int s = t0 % 7;
        const int b = t0 / 7;
        const int l0 = s * 7;
        float* s_pool = u_smem;            // 224 floats
        float* s_wk   = u_smem + 1024;     // 1024 floats
        for (int t = tid; t < 1024; t += 256) s_wk[t] = wk_w[t];
        if (tid < 224) {
            int ic = tid / 7, lj = tid % 7;
            int l = l0 + lj;
            int i = l / 7, j = l % 7;
            const float4* base = (const float4*)(x + (((size_t)b * NC + 32 + ic) * NH + i * 8) * NW + j * 8);
            float sum = 0.f;
            #pragma unroll
            for (int y = 0; y < 8; y++) {
                float4 a = base[y * 14];
                float4 c = base[y * 14 + 1];
                sum += a.x + a.y + a.z + a.w + c.x + c.y + c.z + c.w;
            }
            s_pool[ic * 7 + lj] = sum * (1.0f / 64.0f);
        }
        __syncthreads();
        if (tid < 224) {
            int oc = tid / 7, lj = tid % 7;
            float acc = 0.f;
            #pragma unroll
            for (int ic = 0; ic < 32; ic++)
                acc += s_wk[oc * 32 + ic] * s_pool[ic * 7 + lj];
            kg[(size_t)b * 1568 + oc * 49 + l0 + lj] = acc * wk_s[oc] + wk_b[oc];
        }
    }
}

// WK[b][chan][m] = sum_l wp_w[m*49+l] * kg[b][chan*49+l]   (m padded to 80)
__global__ void k_wk(const float* __restrict__ wp_w,
                     const float* __restrict__ kg,
                     float* __restrict__ wk) {
    const int b = blockIdx.x;
    const int tid = threadIdx.x;
    __shared__ float s_kg[1568];
    __shared__ float s_wp[3626];
    for (int t = tid; t < 1568; t += 256) s_kg[t] = kg[(size_t)b * 1568 + t];
    for (int t = tid; t < 3626; t += 256) s_wp[t] = wp_w[t];
    __syncthreads();
    for (int t = tid; t < 2560; t += 256) {
        int chan = t / 80, m = t % 80;
        float acc = 0.f;
        if (m < 74) {
            const float* wr = s_wp + m * 49;
            const float* kr = s_kg + chan * 49;
            #pragma unroll
            for (int l = 0; l < 49; l++) acc += wr[l] * kr[l];
        }
        wk[(size_t)b * 2560 + t] = acc;
    }
}

__global__ __launch_bounds__(256, 2)
void k_main(const float* __restrict__ x,
            const float* __restrict__ wq_w, const float* __restrict__ wq_s,
            const float* __restrict__ wq_b,
            const float* __restrict__ wp_b,
            const float* __restrict__ rpb1, const float* __restrict__ rpb2,
            const float* __restrict__ dy_w, const float* __restrict__ dy_s,
            const float* __restrict__ dy_b,
            const float* __restrict__ wkmat,
            const float* __restrict__ lep,
            float* __restrict__ out) {
    extern __shared__ float sm[];
    const int h = blockIdx.x;
    const int b = blockIdx.y;
    const int tid = threadIdx.x;

    float* s_wqT  = sm + O_WQT;
    float* s_qb   = sm + O_QB;
    float* s_wpb  = sm + O_WPB;
    float* s_wk   = sm + O_WK;
    float* s_dyw  = sm + O_DYW;
    float* s_dys  = sm + O_DYS;
    float* s_dyb  = sm + O_DYB;
    float* s_rpb1 = sm + O_RPB1;
    float* s_rpb2 = sm + O_RPB2;
    float* s_m    = sm + O_M;
    float2* s_x2  = (float2*)(sm + O_XCH);   // [cq*CQS + rr*64 + wi]

    const int warp = tid >> 5;
    const int lane = tid & 31;

    // ---- P0: stage weights + half0 halo (channels 0..31 -> cq 0..15, rows 1..5) ----
    for (int t = tid; t < 1024; t += 256) {
        int i = t >> 5, o = t & 31;
        s_wqT[t] = wq_w[o * 32 + i] * 0.25f * wq_s[o];
    }
    if (tid < 32) s_qb[tid] = 0.25f * wq_b[tid];
    if (tid < 80) s_wpb[tid] = (tid < 74) ? wp_b[tid] : 0.f;
    for (int t = tid; t < 2560; t += 256) s_wk[t] = wkmat[(size_t)b * 2560 + t];
    for (int t = tid; t < 4096; t += 256) s_dyw[t] = dy_w[t];
    if (tid < 64) { s_dys[tid] = dy_s[tid]; s_dyb[tid] = dy_b[tid]; }
    for (int t = tid; t < 324; t += 256) s_rpb1[t] = rpb1[t];
    for (int t = tid; t < 676; t += 256) s_rpb2[t] = rpb2[t];

    // halo staging: warp handles 2 channel-pairs, lane covers wi and wi+32
    #pragma unroll
    for (int k4 = 0; k4 < 2; k4++) {
        int cq = warp * 2 + k4;
        const float* src0 = x + ((size_t)b * NC + 2 * cq) * (NH * NW);
        const float* src1 = src0 + NH * NW;
        #pragma unroll
        for (int rr = 1; rr <= 5; rr++) {
            int gy = h - 3 + rr;
            bool vy = (unsigned)gy < 56u;
            #pragma unroll
            for (int k = 0; k < 2; k++) {
                int wi = lane + k * 32;
                int gx = wi - 3;
                float v0 = 0.f, v1 = 0.f;
                if (vy && (unsigned)gx < 56u) {
                    v0 = src0[gy * NW + gx];
                    v1 = src1[gy * NW + gx];
                }
                s_x2[cq * CQS + rr * 64 + wi] = make_float2(v0, v1);
            }
        }
    }
    __syncthreads();

    const int p = tid % 56;
    const int g = tid / 56;   // valid when tid < 224

    // ---- P3: q-proj (halo center row) + WK-GEMM (K=8, f32x2) + rpb + softmax ----
    float attn[74];
    if (tid < 224) {
        float qr[8];
        #pragma unroll
        for (int c = 0; c < 8; c++) qr[c] = s_qb[g * 8 + c];
        const float* xf = sm + O_XCH;
        #pragma unroll
        for (int i = 0; i < 32; i++) {
            float xv = xf[((i >> 1) * CQS + 3 * 64 + p + 3) * 2 + (i & 1)];
            const float4* w = (const float4*)(s_wqT + i * 32 + g * 8);
            float4 w0 = w[0], w1 = w[1];
            qr[0] += w0.x * xv; qr[1] += w0.y * xv; qr[2] += w0.z * xv; qr[3] += w0.w * xv;
            qr[4] += w1.x * xv; qr[5] += w1.y * xv; qr[6] += w1.z * xv; qr[7] += w1.w * xv;
        }

        #pragma unroll
        for (int half = 0; half < 2; half++) {
            const int M0 = half * 40;
            unsigned long long acc2[20];
            #pragma unroll
            for (int mm = 0; mm < 20; mm++) {
                float b0 = s_wpb[M0 + 2 * mm], b1 = s_wpb[M0 + 2 * mm + 1];
                asm("mov.b64 %0, {%1, %2};" : "=l"(acc2[mm]) : "f"(b0), "f"(b1));
            }
            #pragma unroll
            for (int c = 0; c < 8; c++) {
                unsigned long long vv;
                asm("mov.b64 %0, {%1, %1};" : "=l"(vv) : "f"(qr[c]));
                const ulonglong2* w2 = (const ulonglong2*)(s_wk + (g * 8 + c) * 80 + M0);
                #pragma unroll
                for (int mm = 0; mm < 10; mm++) {
                    ulonglong2 w = w2[mm];
                    asm("fma.rn.f32x2 %0, %1, %2, %0;" : "+l"(acc2[2 * mm])     : "l"(w.x), "l"(vv));
                    asm("fma.rn.f32x2 %0, %1, %2, %0;" : "+l"(acc2[2 * mm + 1]) : "l"(w.y), "l"(vv));
                }
            }
            #pragma unroll
            for (int mm = 0; mm < 20; mm++) {
                float f0, f1;
                asm("mov.b64 {%0, %1}, %2;" : "=f"(f0), "=f"(f1) : "l"(acc2[mm]));
                int idx = M0 + 2 * mm;
                if (idx < 74)     attn[idx] = f0;
                if (idx + 1 < 74) attn[idx + 1] = f1;
            }
        }

        // relative position bias (derived from numpy _bias_idx incl. [::-1])
        int bh5 = bcl(55 - h, 2, 5), bw5 = bcl(55 - p, 2, 5);
        int bh7 = bcl(55 - h, 3, 7), bw7 = bcl(55 - p, 3, 7);
        const float* r1 = s_rpb1 + g * 81;
        const float* r2 = s_rpb2 + g * 169;
        #pragma unroll
        for (int m = 0; m < 25; m++) {
            int dh = m / 5, dw = m % 5;
            attn[m] += r1[(bh5 + dh) * 9 + bw5 + dw];
        }
        #pragma unroll
        for (int j = 0; j < 49; j++) {
            int dh = j / 7, dw = j % 7;
            attn[25 + j] += r2[(bh7 + dh) * 13 + bw7 + dw];
        }
        // softmax over taps [0,25)
        {
            float mx = -1e30f;
            #pragma unroll
            for (int m = 0; m < 25; m++) mx = fmaxf(mx, attn[m]);
            float s = 0.f;
            #pragma unroll
            for (int m = 0; m < 25; m++) { attn[m] = __expf(attn[m] - mx); s += attn[m]; }
            float inv = 1.0f / s;
            #pragma unroll
            for (int m = 0; m < 25; m++) attn[m] *= inv;
        }
        // softmax over taps [25,74)
        {
            float mx = -1e30f;
            #pragma unroll
            for (int m = 25; m < 74; m++) mx = fmaxf(mx, attn[m]);
            float s = 0.f;
            #pragma unroll
            for (int m = 25; m < 74; m++) { attn[m] = __expf(attn[m] - mx); s += attn[m]; }
            float inv = 1.0f / s;
            #pragma unroll
            for (int m = 25; m < 74; m++) attn[m] *= inv;
        }

        // ---- P5a: 5x5 mixing, 4 channel-pairs via LDS.64 + f32x2 ----
        {
            const unsigned long long* xb =
                (const unsigned long long*)(sm + O_XCH) + (size_t)g * 4 * CQS + p;
            unsigned long long a0 = 0ull, a1 = 0ull, a2 = 0ull, a3 = 0ull;
            #pragma unroll
            for (int dh = 1; dh <= 5; dh++) {
                #pragma unroll
                for (int dw = 1; dw <= 5; dw++) {
                    unsigned long long vv;
                    asm("mov.b64 %0, {%1, %1};" : "=l"(vv) : "f"(attn[(dh - 1) * 5 + (dw - 1)]));
                    unsigned long long x0 = xb[0 * CQS + dh * 64 + dw];
                    unsigned long long x1 = xb[1 * CQS + dh * 64 + dw];
                    unsigned long long x2 = xb[2 * CQS + dh * 64 + dw];
                    unsigned long long x3 = xb[3 * CQS + dh * 64 + dw];
                    asm("fma.rn.f32x2 %0, %1, %2, %0;" : "+l"(a0) : "l"(x0), "l"(vv));
                    asm("fma.rn.f32x2 %0, %1, %2, %0;" : "+l"(a1) : "l"(x1), "l"(vv));
                    asm("fma.rn.f32x2 %0, %1, %2, %0;" : "+l"(a2) : "l"(x2), "l"(vv));
                    asm("fma.rn.f32x2 %0, %1, %2, %0;" : "+l"(a3) : "l"(x3), "l"(vv));
                }
            }
            float2* md = (float2*)(s_m + p * 68 + g * 8);
            float f0, f1;
            asm("mov.b64 {%0, %1}, %2;" : "=f"(f0), "=f"(f1) : "l"(a0)); md[0] = make_float2(f0, f1);
            asm("mov.b64 {%0, %1}, %2;" : "=f"(f0), "=f"(f1) : "l"(a1)); md[1] = make_float2(f0, f1);
            asm("mov.b64 {%0, %1}, %2;" : "=f"(f0), "=f"(f1) : "l"(a2)); md[2] = make_float2(f0, f1);
            asm("mov.b64 {%0, %1}, %2;" : "=f"(f0), "=f"(f1) : "l"(a3)); md[3] = make_float2(f0, f1);
        }
    }
    __syncthreads();   // all half-0 halo reads done

    // ---- stage half1 halo (channels 32..63 -> same cq slots, rows 0..6) ----
    #pragma unroll
    for (int k4 = 0; k4 < 2; k4++) {
        int cq = warp * 2 + k4;
        const float* src0 = x + ((size_t)b * NC + 32 + 2 * cq) * (NH * NW);
        const float* src1 = src0 + NH * NW;
        #pragma unroll
        for (int rr = 0; rr < 7; rr++) {
            int gy = h - 3 + rr;
            bool vy = (unsigned)gy < 56u;
            #pragma unroll
            for (int k = 0; k < 2; k++) {
                int wi = lane + k * 32;
                int gx = wi - 3;
                float v0 = 0.f, v1 = 0.f;
                if (vy && (unsigned)gx < 56u) {
                    v0 = src0[gy * NW + gx];
                    v1 = src1[gy * NW + gx];
                }
                s_x2[cq * CQS + rr * 64 + wi] = make_float2(v0, v1);
            }
        }
    }
    __syncthreads();

    // ---- P5b: 7x7 mixing for the 4 half-1 channel-pairs of group g ----
    if (tid < 224) {
        const unsigned long long* xb =
            (const unsigned long long*)(sm + O_XCH) + (size_t)g * 4 * CQS + p;
        unsigned long long a0 = 0ull, a1 = 0ull, a2 = 0ull, a3 = 0ull;
        #pragma unroll
        for (int dh = 0; dh < 7; dh++) {
            #pragma unroll
            for (int dw = 0; dw < 7; dw++) {
                unsigned long long vv;
                asm("mov.b64 %0, {%1, %1};" : "=l"(vv) : "f"(attn[25 + dh * 7 + dw]));
                unsigned long long x0 = xb[0 * CQS + dh * 64 + dw];
                unsigned long long x1 = xb[1 * CQS + dh * 64 + dw];
                unsigned long long x2 = xb[2 * CQS + dh * 64 + dw];
                unsigned long long x3 = xb[3 * CQS + dh * 64 + dw];
                asm("fma.rn.f32x2 %0, %1, %2, %0;" : "+l"(a0) : "l"(x0), "l"(vv));
                asm("fma.rn.f32x2 %0, %1, %2, %0;" : "+l"(a1) : "l"(x1), "l"(vv));
                asm("fma.rn.f32x2 %0, %1, %2, %0;" : "+l"(a2) : "l"(x2), "l"(vv));
                asm("fma.rn.f32x2 %0, %1, %2, %0;" : "+l"(a3) : "l"(x3), "l"(vv));
            }
        }
        float2* md = (float2*)(s_m + p * 68 + 32 + g * 8);
        float f0, f1;
        asm("mov.b64 {%0, %1}, %2;" : "=f"(f0), "=f"(f1) : "l"(a0)); md[0] = make_float2(f0, f1);
        asm("mov.b64 {%0, %1}, %2;" : "=f"(f0), "=f"(f1) : "l"(a1)); md[1] = make_float2(f0, f1);
        asm("mov.b64 {%0, %1}, %2;" : "=f"(f0), "=f"(f1) : "l"(a2)); md[2] = make_float2(f0, f1);
        asm("mov.b64 {%0, %1}, %2;" : "=f"(f0), "=f"(f1) : "l"(a3)); md[3] = make_float2(f0, f1);
    }
    __syncthreads();

    // ---- P6: dy 64x64 GEMM (float4) + bn + lepe(global) ----
    if (tid < 224) {
        const float* lepb = lep + ((size_t)b * NC) * (NH * NW) + h * NW + p;
        const float4* m4 = (const float4*)(s_m + p * 68);
        #pragma unroll
        for (int k = 0; k < 4; k++) {
            int o0 = (k * 4 + g) * 4;
            float l0 = lepb[(o0 + 0) * 3136];
            float l1 = lepb[(o0 + 1) * 3136];
            float l2 = lepb[(o0 + 2) * 3136];
            float l3 = lepb[(o0 + 3) * 3136];
            const float4* w0 = (const float4*)(s_dyw + (o0 + 0) * 64);
            const float4* w1 = (const float4*)(s_dyw + (o0 + 1) * 64);
            const float4* w2 = (const float4*)(s_dyw + (o0 + 2) * 64);
            const float4* w3 = (const float4*)(s_dyw + (o0 + 3) * 64);
            float a0 = 0.f, a1 = 0.f, a2 = 0.f, a3 = 0.f;
            #pragma unroll
            for (int i = 0; i < 16; i++) {
                float4 mv = m4[i];
                float4 v0 = w0[i], v1 = w1[i], v2 = w2[i], v3 = w3[i];
                a0 += v0.x * mv.x + v0.y * mv.y + v0.z * mv.z + v0.w * mv.w;
                a1 += v1.x * mv.x + v1.y * mv.y + v1.z * mv.z + v1.w * mv.w;
                a2 += v2.x * mv.x + v2.y * mv.y + v2.z * mv.z + v2.w * mv.w;
                a3 += v3.x * mv.x + v3.y * mv.y + v3.z * mv.z + v3.w * mv.w;
            }
            size_t base = (((size_t)b * NC + o0) * NH + h) * NW + p;
            out[base + 0 * 3136] = a0 * s_dys[o0 + 0] + s_dyb[o0 + 0] + l0;
            out[base + 1 * 3136] = a1 * s_dys[o0 + 1] + s_dyb[o0 + 1] + l1;
            out[base + 2 * 3136] = a2 * s_dys[o0 + 2] + s_dyb[o0 + 2] + l2;
            out[base + 3 * 3136] = a3 * s_dys[o0 + 3] + s_dyb[o0 + 3] + l3;
        }
    }
}

extern "C" void kernel_launch(void* const* d_in, const int* in_sizes, int n_in,
                              void* d_out, int out_size) {
    const float* x       = (const float*)d_in[0];
    const float* lepe_w  = (const float*)d_in[1];
    const float* lepe_b  = (const float*)d_in[2];
    const float* lepe_s  = (const float*)d_in[3];
    const float* lepe_bb = (const float*)d_in[4];
    const float* wq_w    = (const float*)d_in[5];
    const float* wq_s    = (const float*)d_in[6];
    const float* wq_b    = (const float*)d_in[7];
    const float* wk_w    = (const float*)d_in[8];
    const float* wk_s    = (const float*)d_in[9];
    const float* wk_b    = (const float*)d_in[10];
    const float* wp_w    = (const float*)d_in[11];
    const float* wp_b    = (const float*)d_in[12];
    const float* rpb1    = (const float*)d_in[13];
    const float* rpb2    = (const float*)d_in[14];
    const float* dy_w    = (const float*)d_in[15];
    const float* dy_s    = (const float*)d_in[16];
    const float* dy_b    = (const float*)d_in[17];
    float* out = (float*)d_out;

    float* kgp = nullptr;
    cudaGetSymbolAddress((void**)&kgp, g_kg);
    float* wkp = nullptr;
    cudaGetSymbolAddress((void**)&wkp, g_wk);
    float* lepp = nullptr;
    cudaGetSymbolAddress((void**)&lepp, g_lep);

    cudaFuncSetAttribute(k_main, cudaFuncAttributeMaxDynamicSharedMemorySize, SMEM_BYTES);

    k_prep<<<1248, 256>>>(x, lepe_w, lepe_b, lepe_s, lepe_bb,
                          wk_w, wk_s, wk_b, lepp, kgp);
    k_wk<<<NB, 256>>>(wp_w, kgp, wkp);
    k_main<<<dim3(NH, NB), 256, SMEM_BYTES>>>(
        x, wq_w, wq_s, wq_b, wp_b,
        rpb1, rpb2, dy_w, dy_s, dy_b, wkp, lepp, out);
}